// round 6
// baseline (speedup 1.0000x reference)
#include <cuda_runtime.h>
#include <cuda_fp16.h>

#define BS    512
#define NN    256
#define MAXIT 200
#define OMEGA 1.5f

// fp32 G (solve-accurate, read by left-looking updates), fp16 copy for iteration.
__device__ float  g_G [(size_t)BS * NN * NN];   // 128 MB
__device__ __half g_Gh[(size_t)BS * NN * NN];   // 64 MB (L2-resident)
__device__ float  g_E[BS * NN];
__device__ int    g_tc[BS];
__device__ int    g_T;

__device__ __forceinline__ float warp_sum(float v) {
#pragma unroll
    for (int o = 16; o > 0; o >>= 1) v += __shfl_xor_sync(0xffffffffu, v, o);
    return v;
}

// ---------------------------------------------------------------------------
// k_pre: solve (D + wL) G = -(wU + (w-1)D), 256 RHS columns per batch.
// CTA = 128 threads = 2 independent batches x 64 threads; thread owns 4
// columns -> each shL element feeds 4 FMAs (FFMA-issue-bound mix).
// Control flow is identical for both halves, so __syncthreads() aligns.
// ---------------------------------------------------------------------------
__global__ void __launch_bounds__(128) k_pre(const float* __restrict__ A) {
    __shared__ float shL[2][32][33];
    __shared__ float sh_invd[2][NN];
    int half = threadIdx.x >> 6;           // which batch of the pair
    int t    = threadIdx.x & 63;           // thread within half
    int b    = blockIdx.x * 2 + half;
    int c0   = 4 * t;
    const float* Ab = A    + (size_t)b * NN * NN;
    float*       Gb = g_G  + (size_t)b * NN * NN;
    __half*      Gh = g_Gh + (size_t)b * NN * NN;
    float (*L)[33]  = shL[half];
    float* invd     = sh_invd[half];

    for (int i = t; i < NN; i += 64)
        invd[i] = 1.0f / Ab[(size_t)i * NN + i];
    if (b == 0 && threadIdx.x == 0) g_T = 0;   // reset before phase-0 atomicMax
    __syncthreads();

    float acc0[32], acc1[32], acc2[32], acc3[32];

#pragma unroll 1
    for (int blk = 0; blk < 8; blk++) {
        int r0 = blk * 32;
        // RHS init: -(wU + (w-1)D) rows r0..r0+31, cols c0..c0+3 (coalesced).
#pragma unroll
        for (int k = 0; k < 32; k++) {
            int r = r0 + k;
            float4 a = *reinterpret_cast<const float4*>(Ab + (size_t)r * NN + c0);
            acc0[k] = (c0     > r) ? -OMEGA * a.x : ((c0     == r) ? -(OMEGA - 1.f) * a.x : 0.f);
            acc1[k] = (c0 + 1 > r) ? -OMEGA * a.y : ((c0 + 1 == r) ? -(OMEGA - 1.f) * a.y : 0.f);
            acc2[k] = (c0 + 2 > r) ? -OMEGA * a.z : ((c0 + 2 == r) ? -(OMEGA - 1.f) * a.z : 0.f);
            acc3[k] = (c0 + 3 > r) ? -OMEGA * a.w : ((c0 + 3 == r) ? -(OMEGA - 1.f) * a.w : 0.f);
        }
        // Left-looking update with already-solved rows (32-wide j tiles).
#pragma unroll 1
        for (int j0 = 0; j0 < r0; j0 += 32) {
            __syncthreads();
            for (int e = t; e < 32 * 32; e += 64) {
                int k = e >> 5, jj = e & 31;
                L[k][jj] = OMEGA * Ab[(size_t)(r0 + k) * NN + j0 + jj];
            }
            __syncthreads();
            float4 yv = *reinterpret_cast<const float4*>(Gb + (size_t)j0 * NN + c0);
#pragma unroll 2
            for (int jj = 0; jj < 32; jj++) {
                float4 yn;
                if (jj < 31)                       // prefetch next column row
                    yn = *reinterpret_cast<const float4*>(Gb + (size_t)(j0 + jj + 1) * NN + c0);
#pragma unroll
                for (int k = 0; k < 32; k++) {
                    float l = L[k][jj];
                    acc0[k] = fmaf(-l, yv.x, acc0[k]);
                    acc1[k] = fmaf(-l, yv.y, acc1[k]);
                    acc2[k] = fmaf(-l, yv.z, acc2[k]);
                    acc3[k] = fmaf(-l, yv.w, acc3[k]);
                }
                yv = yn;
            }
        }
        // Diagonal 32x32 block: serial triangular solve, 4 columns in flight.
        __syncthreads();
        for (int e = t; e < 32 * 32; e += 64) {
            int k = e >> 5, jj = e & 31;
            L[k][jj] = OMEGA * Ab[(size_t)(r0 + k) * NN + r0 + jj];
        }
        __syncthreads();
#pragma unroll
        for (int k = 0; k < 32; k++) {
            float inv = invd[r0 + k];
            float y0 = acc0[k] * inv, y1 = acc1[k] * inv;
            float y2 = acc2[k] * inv, y3 = acc3[k] * inv;
            *reinterpret_cast<float4*>(Gb + (size_t)(r0 + k) * NN + c0) =
                make_float4(y0, y1, y2, y3);
            __half2 h01 = __floats2half2_rn(y0, y1);
            __half2 h23 = __floats2half2_rn(y2, y3);
            *reinterpret_cast<__half2*>(Gh + (size_t)(r0 + k) * NN + c0)     = h01;
            *reinterpret_cast<__half2*>(Gh + (size_t)(r0 + k) * NN + c0 + 2) = h23;
#pragma unroll
            for (int m = k + 1; m < 32; m++) {
                float l = L[m][k];
                acc0[m] = fmaf(-l, y0, acc0[m]);
                acc1[m] = fmaf(-l, y1, acc1[m]);
                acc2[m] = fmaf(-l, y2, acc2[m]);
                acc3[m] = fmaf(-l, y3, acc3[m]);
            }
        }
    }
}

// ---------------------------------------------------------------------------
// One e <- G e step on fp16 G, fp32 accumulation. CTA = 8 warps; warp w owns
// rows [32w, 32w+32); lane reads 8 cols (16B). Returns ||e_new|| (CTA-uniform).
// ---------------------------------------------------------------------------
__device__ float iter_step(const __half* __restrict__ Gh, float* e_sm, float* red,
                           int wid, int lane) {
    float4 ev0 = *reinterpret_cast<const float4*>(&e_sm[lane * 8]);
    float4 ev1 = *reinterpret_cast<const float4*>(&e_sm[lane * 8 + 4]);
    float myval = 0.0f;
#pragma unroll 4
    for (int rr = 0; rr < 32; rr++) {
        int row = (wid << 5) + rr;
        uint4 raw = *reinterpret_cast<const uint4*>(Gh + (size_t)row * NN + lane * 8);
        float2 f0 = __half22float2(*reinterpret_cast<__half2*>(&raw.x));
        float2 f1 = __half22float2(*reinterpret_cast<__half2*>(&raw.y));
        float2 f2 = __half22float2(*reinterpret_cast<__half2*>(&raw.z));
        float2 f3 = __half22float2(*reinterpret_cast<__half2*>(&raw.w));
        float s = f0.x * ev0.x + f0.y * ev0.y + f1.x * ev0.z + f1.y * ev0.w
                + f2.x * ev1.x + f2.y * ev1.y + f3.x * ev1.z + f3.y * ev1.w;
        s = warp_sum(s);
        if (lane == rr) myval = s;
    }
    __syncthreads();                              // all e_sm reads done
    e_sm[(wid << 5) + lane] = myval;
    float p = warp_sum(myval * myval);
    if (lane == 0) red[wid] = p;
    __syncthreads();
    float tot = red[0] + red[1] + red[2] + red[3] + red[4] + red[5] + red[6] + red[7];
    return sqrtf(tot);
}

// ---------------------------------------------------------------------------
// phase 0: per batch iterate until own err <= xtol; record t_b, atomicMax T.
// phase 1: resume from saved state to global T; zero tail columns.
// ---------------------------------------------------------------------------
__global__ void __launch_bounds__(256) k_iter(const float* __restrict__ xsol,
                                              const float* __restrict__ theta,
                                              const float* __restrict__ rtol,
                                              float* __restrict__ out, int phase) {
    __shared__ float e_sm[NN];
    __shared__ float red[8];
    int b = blockIdx.x;
    int tid = threadIdx.x, wid = tid >> 5, lane = tid & 31;
    const __half* Gh   = g_Gh + (size_t)b * NN * NN;
    float*        outb = out  + (size_t)b * (MAXIT + 1);

    float xv = xsol[b * NN + tid];
    float p = warp_sum(xv * xv);
    if (lane == 0) red[wid] = p;
    __syncthreads();
    float xtol = rtol[b] * sqrtf(red[0] + red[1] + red[2] + red[3] +
                                 red[4] + red[5] + red[6] + red[7]);
    __syncthreads();

    if (phase == 0) {
        float e0 = theta[b * NN + tid] - xv;
        e_sm[tid] = e0;
        float q = warp_sum(e0 * e0);
        if (lane == 0) red[wid] = q;
        __syncthreads();
        float err = sqrtf(red[0] + red[1] + red[2] + red[3] +
                          red[4] + red[5] + red[6] + red[7]);
        if (tid == 0) outb[0] = err;
        __syncthreads();
        int t = 0;
        while (err > xtol && t < MAXIT) {         // err uniform across CTA
            t++;
            err = iter_step(Gh, e_sm, red, wid, lane);
            if (tid == 0) outb[t] = err;
        }
        g_E[b * NN + tid] = e_sm[tid];
        if (tid == 0) { g_tc[b] = t; atomicMax(&g_T, t); }
    } else {
        int T = g_T, t = g_tc[b];
        e_sm[tid] = g_E[b * NN + tid];
        __syncthreads();
        while (t < T) {
            t++;
            float err = iter_step(Gh, e_sm, red, wid, lane);
            if (tid == 0) outb[t] = err;
        }
        for (int t2 = T + 1 + tid; t2 <= MAXIT; t2 += 256) outb[t2] = 0.0f;
    }
}

extern "C" void kernel_launch(void* const* d_in, const int* in_sizes, int n_in,
                              void* d_out, int out_size) {
    const float* A     = (const float*)d_in[0];
    const float* xsol  = (const float*)d_in[2];
    const float* theta = (const float*)d_in[3];
    const float* rtol  = (const float*)d_in[4];
    float*       out   = (float*)d_out;

    k_pre <<<BS / 2, 128>>>(A);
    k_iter<<<BS, 256>>>(xsol, theta, rtol, out, 0);
    k_iter<<<BS, 256>>>(xsol, theta, rtol, out, 1);
}

// round 7
// speedup vs baseline: 3.0743x; 3.0743x over previous
#include <cuda_runtime.h>
#include <cuda_fp16.h>

#define BS    512
#define NN    256
#define MAXIT 200
#define OMEGA 1.5f

// fp16 packed transpose of omega*A: AT2[b][jp][i] = (wA[i][2jp], wA[i][2jp+1]).
// 64 MB -> L2-resident. Diagonal handled separately in fp32.
__device__ __half2 g_AT2[(size_t)BS * (NN / 2) * NN];
__device__ float   g_E[BS * NN];
__device__ int     g_tc[BS];
__device__ int     g_T;

__device__ __forceinline__ float warp_sum(float v) {
#pragma unroll
    for (int o = 16; o > 0; o >>= 1) v += __shfl_xor_sync(0xffffffffu, v, o);
    return v;
}

// ---------------------------------------------------------------------------
// k_conv: A -> fp16 omega*A^T, packed as half2 over column pairs. Resets g_T.
// ---------------------------------------------------------------------------
__global__ void k_conv(const float* __restrict__ A) {
    __shared__ float tile[32][33];
    int b = blockIdx.z, i0 = blockIdx.x * 32, j0 = blockIdx.y * 32;
    const float* Ab = A + (size_t)b * NN * NN;
    __half2*    ATb = g_AT2 + (size_t)b * (NN / 2) * NN;
#pragma unroll
    for (int r = threadIdx.y; r < 32; r += 8)      // tile[irel][jrel]
        tile[r][threadIdx.x] = Ab[(size_t)(i0 + r) * NN + j0 + threadIdx.x];
    __syncthreads();
    int i = i0 + threadIdx.x;
#pragma unroll
    for (int p = threadIdx.y; p < 16; p += 8) {    // jp pair within tile
        int jp = (j0 >> 1) + p;
        ATb[(size_t)jp * NN + i] =
            __floats2half2_rn(OMEGA * tile[threadIdx.x][2 * p],
                              OMEGA * tile[threadIdx.x][2 * p + 1]);
    }
    if (blockIdx.x == 0 && blockIdx.y == 0 && blockIdx.z == 0 &&
        threadIdx.x == 0 && threadIdx.y == 0)
        g_T = 0;
}

// ---------------------------------------------------------------------------
// One SOR sweep on e (homogeneous): (D+wL)e' = ((1-w)D - wU)e.
// Thread i = row i; warp blk solves rows [32blk,32blk+32) by shfl chain using
// preloaded diag-block coefficients wa[32]; later warps fold finished blocks.
// Returns ||e'|| (CTA-uniform). e_sm updated in place.
// ---------------------------------------------------------------------------
__device__ float sweep(const __half2* __restrict__ AT2, float* e_sm, float* red,
                       const float* wa, float invd, float dc,
                       int i, int wid, int lane) {
    // RHS: acc = (1-w)d_i e_i - sum_{j>i} wA[i][j] e[j]   (old e)
    float acc = dc * e_sm[i];
    if (!(i & 1)) {                                   // boundary pair jp = i/2
        __half2 a2 = AT2[(size_t)(i >> 1) * NN + i];
        acc = fmaf(-__high2float(a2), e_sm[i + 1], acc);
    }
#pragma unroll 4
    for (int jp = (i >> 1) + 1; jp < NN / 2; jp++) {
        float2 a = __half22float2(AT2[(size_t)jp * NN + i]);
        float2 e2 = *reinterpret_cast<const float2*>(&e_sm[2 * jp]);
        acc = fmaf(-a.x, e2.x, acc);
        acc = fmaf(-a.y, e2.y, acc);
    }
    __syncthreads();                                  // all old-e reads done

    // Forward substitution, 8 blocks of 32 rows.
    float ep = 0.0f;
#pragma unroll 1
    for (int blk = 0; blk < 8; blk++) {
        if (wid == blk) {                             // my block: shfl solve
            float x = 0.0f;
#pragma unroll
            for (int k = 0; k < 32; k++) {
                float xk = __shfl_sync(0xffffffffu, acc * invd, k);
                if (lane == k) x = xk;
                if (lane > k) acc = fmaf(-wa[k], xk, acc);
            }
            ep = x;
            e_sm[i] = x;
        }
        __syncthreads();                              // block's e' published
        if (wid > blk) {                              // fold finished block
            int jp0 = blk * 16;
#pragma unroll
            for (int m = 0; m < 16; m++) {
                float2 a = __half22float2(AT2[(size_t)(jp0 + m) * NN + i]);
                float2 e2 = *reinterpret_cast<const float2*>(&e_sm[2 * (jp0 + m)]);
                acc = fmaf(-a.x, e2.x, acc);
                acc = fmaf(-a.y, e2.y, acc);
            }
        }
    }
    // err = ||e'||
    float p = warp_sum(ep * ep);
    if (lane == 0) red[wid] = p;
    __syncthreads();
    float tot = red[0] + red[1] + red[2] + red[3] + red[4] + red[5] + red[6] + red[7];
    return sqrtf(tot);
}

// ---------------------------------------------------------------------------
// phase 0: per batch iterate until own err <= xtol; record t_b, atomicMax T.
// phase 1: resume from saved state to global T; zero tail columns.
// ---------------------------------------------------------------------------
__global__ void __launch_bounds__(256) k_sor(const float* __restrict__ A,
                                             const float* __restrict__ xsol,
                                             const float* __restrict__ theta,
                                             const float* __restrict__ rtol,
                                             float* __restrict__ out, int phase) {
    __shared__ float e_sm[NN];
    __shared__ float red[8];
    int b = blockIdx.x;
    int i = threadIdx.x, wid = i >> 5, lane = i & 31;
    const float*   Ab  = A     + (size_t)b * NN * NN;
    const __half2* AT2 = g_AT2 + (size_t)b * (NN / 2) * NN;
    float*        outb = out   + (size_t)b * (MAXIT + 1);

    // Per-row constants: diag (fp32), preloaded diag-block lower coefficients.
    float d    = Ab[(size_t)i * NN + i];
    float invd = 1.0f / d;
    float dc   = (1.0f - OMEGA) * d;
    float wa[32];                                     // wA[i][rb..rb+31], fp32
    {
        int rbp = (i >> 5) << 4;                      // block base / 2
#pragma unroll
        for (int m = 0; m < 16; m++) {
            float2 a = __half22float2(AT2[(size_t)(rbp + m) * NN + i]);
            wa[2 * m] = a.x;
            wa[2 * m + 1] = a.y;
        }
    }

    float xv = xsol[b * NN + i];
    float p = warp_sum(xv * xv);
    if (lane == 0) red[wid] = p;
    __syncthreads();
    float xtol = rtol[b] * sqrtf(red[0] + red[1] + red[2] + red[3] +
                                 red[4] + red[5] + red[6] + red[7]);
    __syncthreads();

    if (phase == 0) {
        float e0 = theta[b * NN + i] - xv;
        e_sm[i] = e0;
        float q = warp_sum(e0 * e0);
        if (lane == 0) red[wid] = q;
        __syncthreads();
        float err = sqrtf(red[0] + red[1] + red[2] + red[3] +
                          red[4] + red[5] + red[6] + red[7]);
        if (i == 0) outb[0] = err;
        __syncthreads();
        int t = 0;
        while (err > xtol && t < MAXIT) {             // err CTA-uniform
            t++;
            err = sweep(AT2, e_sm, red, wa, invd, dc, i, wid, lane);
            if (i == 0) outb[t] = err;
            __syncthreads();                          // red reuse guard
        }
        g_E[b * NN + i] = e_sm[i];
        if (i == 0) { g_tc[b] = t; atomicMax(&g_T, t); }
    } else {
        int T = g_T, t = g_tc[b];
        e_sm[i] = g_E[b * NN + i];
        __syncthreads();
        while (t < T) {
            t++;
            float err = sweep(AT2, e_sm, red, wa, invd, dc, i, wid, lane);
            if (i == 0) outb[t] = err;
            __syncthreads();
        }
        for (int t2 = T + 1 + i; t2 <= MAXIT; t2 += 256) outb[t2] = 0.0f;
    }
}

extern "C" void kernel_launch(void* const* d_in, const int* in_sizes, int n_in,
                              void* d_out, int out_size) {
    const float* A     = (const float*)d_in[0];
    const float* xsol  = (const float*)d_in[2];
    const float* theta = (const float*)d_in[3];
    const float* rtol  = (const float*)d_in[4];
    float*       out   = (float*)d_out;

    k_conv<<<dim3(NN / 32, NN / 32, BS), dim3(32, 8)>>>(A);
    k_sor<<<BS, 256>>>(A, xsol, theta, rtol, out, 0);
    k_sor<<<BS, 256>>>(A, xsol, theta, rtol, out, 1);
}

// round 8
// speedup vs baseline: 4.0199x; 1.3076x over previous
#include <cuda_runtime.h>
#include <cuda_fp16.h>

#define BS    512
#define NN    256
#define NP2   (NN / 2)
#define MAXIT 200
#define OMEGA 1.5f

// fp16 packed transpose of omega*A: AT2[b][jp][i] = (wA[i][2jp], wA[i][2jp+1]).
// 64 MB -> L2-resident across sweeps.
__device__ __half2 g_AT2[(size_t)BS * NP2 * NN];
__device__ float   g_E[BS * NN];
__device__ int     g_tc[BS];
__device__ int     g_T;

__device__ __forceinline__ float warp_sum(float v) {
#pragma unroll
    for (int o = 16; o > 0; o >>= 1) v += __shfl_xor_sync(0xffffffffu, v, o);
    return v;
}

// ---------------------------------------------------------------------------
// k_conv: A -> fp16 omega*A^T, packed half2 over column pairs. Resets g_T.
// ---------------------------------------------------------------------------
__global__ void k_conv(const float* __restrict__ A) {
    __shared__ float tile[32][33];
    int b = blockIdx.z, i0 = blockIdx.x * 32, j0 = blockIdx.y * 32;
    const float* Ab = A + (size_t)b * NN * NN;
    __half2*    ATb = g_AT2 + (size_t)b * NP2 * NN;
#pragma unroll
    for (int r = threadIdx.y; r < 32; r += 8)
        tile[r][threadIdx.x] = Ab[(size_t)(i0 + r) * NN + j0 + threadIdx.x];
    __syncthreads();
    int i = i0 + threadIdx.x;
#pragma unroll
    for (int p = threadIdx.y; p < 16; p += 8) {
        int jp = (j0 >> 1) + p;
        ATb[(size_t)jp * NN + i] =
            __floats2half2_rn(OMEGA * tile[threadIdx.x][2 * p],
                              OMEGA * tile[threadIdx.x][2 * p + 1]);
    }
    if (blockIdx.x == 0 && blockIdx.y == 0 && blockIdx.z == 0 &&
        threadIdx.x == 0 && threadIdx.y == 0)
        g_T = 0;
}

// ---------------------------------------------------------------------------
// One sweep: (D+wL)e' = ((1-w)D - wU)e.  Thread i = row i.  Block solve via
// preinverted 32x32 diag blocks (binv = lane's row, registers); folds use
// register-prefetched fp16 coefficients. Returns ||e'|| (CTA-uniform).
// ---------------------------------------------------------------------------
__device__ float sweep(const __half2* __restrict__ AT2, float* e_sm, float* red,
                       const float* binv, float dc, int i, int wid, int lane) {
    // RHS with OLD e: acc = (1-w)d_i e_i - sum_{j>i} wA[i][j] e_j
    float acc = dc * e_sm[i];
    if (!(i & 1)) {
        __half2 a2 = AT2[(size_t)(i >> 1) * NN + i];
        acc = fmaf(-__high2float(a2), e_sm[i + 1], acc);
    }
#pragma unroll 8
    for (int jp = (i >> 1) + 1; jp < NP2; jp++) {
        float2 a = __half22float2(AT2[(size_t)jp * NN + i]);
        float2 e2 = *reinterpret_cast<const float2*>(&e_sm[2 * jp]);
        acc = fmaf(-a.x, e2.x, acc);
        acc = fmaf(-a.y, e2.y, acc);
    }
    // Prefetch fold coefficients for block 0.
    __half2 pf[16];
    if (wid > 0) {
#pragma unroll
        for (int m = 0; m < 16; m++) pf[m] = AT2[(size_t)m * NN + i];
    }
    __syncthreads();                                  // all old-e reads done

    float ep = 0.0f;
#pragma unroll 1
    for (int blk = 0; blk < 8; blk++) {
        if (wid == blk) {                             // chain-free block solve
            float x = 0.0f;
#pragma unroll
            for (int k = 0; k < 32; k++)
                x = fmaf(binv[k], __shfl_sync(0xffffffffu, acc, k), x);
            ep = x;
            e_sm[i] = x;
        }
        __syncthreads();                              // block's e' published
        if (wid > blk) {                              // fold with prefetched coefs
#pragma unroll
            for (int m = 0; m < 16; m++) {
                float2 a = __half22float2(pf[m]);
                float2 e2 = *reinterpret_cast<const float2*>(&e_sm[2 * (16 * blk + m)]);
                acc = fmaf(-a.x, e2.x, acc);
                acc = fmaf(-a.y, e2.y, acc);
            }
            if (wid > blk + 1) {                      // prefetch next block
#pragma unroll
                for (int m = 0; m < 16; m++)
                    pf[m] = AT2[(size_t)((blk + 1) * 16 + m) * NN + i];
            }
        }
    }
    float p = warp_sum(ep * ep);
    if (lane == 0) red[wid] = p;
    __syncthreads();
    float tot = red[0] + red[1] + red[2] + red[3] + red[4] + red[5] + red[6] + red[7];
    return sqrtf(tot);
}

// ---------------------------------------------------------------------------
// phase 0: iterate each batch to its own convergence; record t_b, atomicMax T.
// phase 1: resume from saved state to global T; zero tail columns.
// ---------------------------------------------------------------------------
__global__ void __launch_bounds__(256) k_sor(const float* __restrict__ A,
                                             const float* __restrict__ xsol,
                                             const float* __restrict__ theta,
                                             const float* __restrict__ rtol,
                                             float* __restrict__ out, int phase) {
    __shared__ float tiles[8][32][33];                // fp32 diag blocks (init only)
    __shared__ float e_sm[NN];
    __shared__ float red[8];
    int b = blockIdx.x;
    int i = threadIdx.x, wid = i >> 5, lane = i & 31;
    const float*   Ab  = A     + (size_t)b * NN * NN;
    const __half2* AT2 = g_AT2 + (size_t)b * NP2 * NN;
    float*        outb = out   + (size_t)b * (MAXIT + 1);

    // ---- init: load fp32 diag block T (lower+diag), invert rows in-register.
    float (*T)[33] = tiles[wid];
#pragma unroll 4
    for (int k = 0; k < 32; k++) {
        float v = Ab[(size_t)(32 * wid + k) * NN + 32 * wid + lane];
        T[k][lane] = (lane < k) ? OMEGA * v : ((lane == k) ? v : 0.0f);
    }
    __syncwarp();
    float dc = (1.0f - OMEGA) * T[lane][lane];
    float binv[32];                                   // row `lane` of T^{-1}
#pragma unroll
    for (int j = 31; j >= 0; j--) {
        float s = (j == lane) ? 1.0f : 0.0f;
#pragma unroll
        for (int k = j + 1; k < 32; k++)
            s = fmaf(-T[k][j], binv[k], s);
        binv[j] = (j <= lane) ? s / T[j][j] : 0.0f;
    }

    float xv = xsol[b * NN + i];
    float p = warp_sum(xv * xv);
    if (lane == 0) red[wid] = p;
    __syncthreads();
    float xtol = rtol[b] * sqrtf(red[0] + red[1] + red[2] + red[3] +
                                 red[4] + red[5] + red[6] + red[7]);
    __syncthreads();

    if (phase == 0) {
        float e0 = theta[b * NN + i] - xv;
        e_sm[i] = e0;
        float q = warp_sum(e0 * e0);
        if (lane == 0) red[wid] = q;
        __syncthreads();
        float err = sqrtf(red[0] + red[1] + red[2] + red[3] +
                          red[4] + red[5] + red[6] + red[7]);
        if (i == 0) outb[0] = err;
        __syncthreads();
        int t = 0;
        while (err > xtol && t < MAXIT) {             // err CTA-uniform
            t++;
            err = sweep(AT2, e_sm, red, binv, dc, i, wid, lane);
            if (i == 0) outb[t] = err;
            __syncthreads();                          // red reuse guard
        }
        g_E[b * NN + i] = e_sm[i];
        if (i == 0) { g_tc[b] = t; atomicMax(&g_T, t); }
    } else {
        int T2 = g_T, t = g_tc[b];
        e_sm[i] = g_E[b * NN + i];
        __syncthreads();
        while (t < T2) {
            t++;
            float err = sweep(AT2, e_sm, red, binv, dc, i, wid, lane);
            if (i == 0) outb[t] = err;
            __syncthreads();
        }
        for (int t2 = T2 + 1 + i; t2 <= MAXIT; t2 += 256) outb[t2] = 0.0f;
    }
}

extern "C" void kernel_launch(void* const* d_in, const int* in_sizes, int n_in,
                              void* d_out, int out_size) {
    const float* A     = (const float*)d_in[0];
    const float* xsol  = (const float*)d_in[2];
    const float* theta = (const float*)d_in[3];
    const float* rtol  = (const float*)d_in[4];
    float*       out   = (float*)d_out;

    k_conv<<<dim3(NN / 32, NN / 32, BS), dim3(32, 8)>>>(A);
    k_sor<<<BS, 256>>>(A, xsol, theta, rtol, out, 0);
    k_sor<<<BS, 256>>>(A, xsol, theta, rtol, out, 1);
}